// round 17
// baseline (speedup 1.0000x reference)
#include <cuda_runtime.h>
#include <math.h>

#define NB  16
#define C   256
#define H   80
#define W   80
#define MIP 8
#define L   160            // H + W
#define BN_EPS 1e-5f

#define PF_BLOCKS 256      // prefetch blocks appended to k2's grid.x
#define PF_PLANES 1024     // planes 0..1023 re-warmed into L2 (k3 reads them last)

// Scratch (device globals: no allocations allowed)
__device__ float g_y [NB * C * L];   // [n][c][l]: l<80 row means (x_h), l>=80 col means (x_w)
__device__ float g_ah[NB * C * H];
__device__ float g_aw[NB * C * W];

__device__ __forceinline__ float fsig(float v) { return 1.f / (1.f + __expf(-v)); }

// Touch a 16B chunk of global memory (insert/refresh in L2), discard the data.
__device__ __forceinline__ void touch16(const float4* p) {
    float a, b, c, d;
    asm volatile("ld.global.nc.v4.f32 {%0,%1,%2,%3}, [%4];"
                 : "=f"(a), "=f"(b), "=f"(c), "=f"(d) : "l"(p));
}

// ---------------------------------------------------------------------------
// k1 (R7-proven, ~20us @ 5.3 TB/s): one block (320 thr) per plane, ascending.
// ---------------------------------------------------------------------------
__global__ __launch_bounds__(320) void k1_means(const float* __restrict__ x) {
    __shared__ float s_row[H][21];     // 21: gcd(21,32)=1
    __shared__ float s_col[W][17];     // 17: gcd(17,32)=1
    const int plane = blockIdx.x;
    const int t  = threadIdx.x;
    const int q  = t % 20;             // float4 column group
    const int rg = t / 20;             // row group 0..15
    const float4* __restrict__ xp = (const float4*)(x + (size_t)plane * (H * W));

    float4 cacc = make_float4(0.f, 0.f, 0.f, 0.f);
    #pragma unroll
    for (int i = 0; i < 5; i++) {
        int r = i * 16 + rg;
        float4 v = xp[r * 20 + q];
        cacc.x += v.x; cacc.y += v.y; cacc.z += v.z; cacc.w += v.w;
        s_row[r][q] = v.x + v.y + v.z + v.w;
    }
    s_col[4 * q + 0][rg] = cacc.x;
    s_col[4 * q + 1][rg] = cacc.y;
    s_col[4 * q + 2][rg] = cacc.z;
    s_col[4 * q + 3][rg] = cacc.w;
    __syncthreads();

    const float inv80 = 1.0f / 80.0f;
    if (t < H) {
        float s = 0.f;
        #pragma unroll
        for (int j = 0; j < 20; j++) s += s_row[t][j];
        g_y[(size_t)plane * L + t] = s * inv80;          // x_h (row mean)
    } else if (t >= 160 && t < 160 + W) {
        int col = t - 160;
        float s = 0.f;
        #pragma unroll
        for (int g = 0; g < 16; g++) s += s_col[col][g];
        g_y[(size_t)plane * L + H + col] = s * inv80;    // x_w (col mean)
    }
}

// ---------------------------------------------------------------------------
// k2: grid (16 + PF_BLOCKS, 2), block 320.
//   blockIdx.x <  16 : R7-proven attention math (unchanged).
//   blockIdx.x >= 16 : prefetch role — re-warm x planes 0..PF_PLANES-1 into L2
//                      during k2's latency shadow (DRAM is otherwise idle).
// ---------------------------------------------------------------------------
__global__ __launch_bounds__(320) void k2_attn(const float* __restrict__ x,
                                               const float* __restrict__ w_fc,
                                               const float* __restrict__ bn_gamma,
                                               const float* __restrict__ bn_beta,
                                               const float* __restrict__ bn_mean,
                                               const float* __restrict__ bn_var,
                                               const float* __restrict__ w_h,
                                               const float* __restrict__ w_w) {
    const int t = threadIdx.x;

    if (blockIdx.x >= 16) {
        // ---- prefetch role: 2 planes per (block, y) -> PF_BLOCKS*2*2 = 1024 planes
        const int pfi = (blockIdx.x - 16) + PF_BLOCKS * blockIdx.y;   // 0..511
        const float4* base = (const float4*)x + (size_t)pfi * 2 * 1600;
        #pragma unroll
        for (int i = 0; i < 10; i++)                      // 2*1600/320 = 10 per thread
            touch16(base + i * 320 + t);
        return;
    }

    __shared__ float ys[MIP * L];        // swished bottleneck (5 KB)
    __shared__ float wfcT[C * MIP];      // w_fc transposed (8 KB)
    __shared__ float ps[2 * MIP * L];    // split-K partials (10 KB)
    const int n = blockIdx.x;

    if (t < C) {
        #pragma unroll
        for (int m = 0; m < MIP; m++) wfcT[t * MIP + m] = w_fc[m * C + t];
    }
    __syncthreads();

    const float* __restrict__ yb = g_y + (size_t)n * C * L;
    {
        const int l    = t % L;
        const int half = t / L;                          // 0 or 1
        const int c0   = half * (C / 2);
        float acc[MIP];
        #pragma unroll
        for (int m = 0; m < MIP; m++) acc[m] = 0.f;
        #pragma unroll 8
        for (int c = 0; c < C / 2; c++) {
            float v = yb[(c0 + c) * L + l];              // coalesced across threads
            const float4* wr = (const float4*)(wfcT + (c0 + c) * MIP);
            float4 a = wr[0], b = wr[1];
            acc[0] = fmaf(a.x, v, acc[0]); acc[1] = fmaf(a.y, v, acc[1]);
            acc[2] = fmaf(a.z, v, acc[2]); acc[3] = fmaf(a.w, v, acc[3]);
            acc[4] = fmaf(b.x, v, acc[4]); acc[5] = fmaf(b.y, v, acc[5]);
            acc[6] = fmaf(b.z, v, acc[6]); acc[7] = fmaf(b.w, v, acc[7]);
        }
        #pragma unroll
        for (int m = 0; m < MIP; m++) ps[half * MIP * L + m * L + l] = acc[m];
    }
    __syncthreads();

    if (t < L) {
        #pragma unroll
        for (int m = 0; m < MIP; m++) {
            float s  = ps[m * L + t] + ps[MIP * L + m * L + t];
            float iv = bn_gamma[m] * rsqrtf(bn_var[m] + BN_EPS);
            float vv = s * iv + (bn_beta[m] - bn_mean[m] * iv);
            ys[m * L + t] = vv * fsig(vv);
        }
    }
    __syncthreads();

    const int l  = t % 80;
    const int cg = t / 80;                               // 0..3
    const int c0 = (blockIdx.y * 4 + cg) * 32;
    float yh[MIP], yw[MIP];
    #pragma unroll
    for (int m = 0; m < MIP; m++) { yh[m] = ys[m * L + l]; yw[m] = ys[m * L + H + l]; }

    float* __restrict__ ahp = g_ah + (size_t)n * C * H;
    float* __restrict__ awp = g_aw + (size_t)n * C * W;
    #pragma unroll 4
    for (int c = c0; c < c0 + 32; c++) {
        const float4* wh4 = (const float4*)(w_h + c * MIP);
        const float4* ww4 = (const float4*)(w_w + c * MIP);
        float4 ha = wh4[0], hb = wh4[1];
        float4 wa = ww4[0], wb = ww4[1];
        float sh = 0.f, sw = 0.f;
        sh = fmaf(ha.x, yh[0], sh); sh = fmaf(ha.y, yh[1], sh);
        sh = fmaf(ha.z, yh[2], sh); sh = fmaf(ha.w, yh[3], sh);
        sh = fmaf(hb.x, yh[4], sh); sh = fmaf(hb.y, yh[5], sh);
        sh = fmaf(hb.z, yh[6], sh); sh = fmaf(hb.w, yh[7], sh);
        sw = fmaf(wa.x, yw[0], sw); sw = fmaf(wa.y, yw[1], sw);
        sw = fmaf(wa.z, yw[2], sw); sw = fmaf(wa.w, yw[3], sw);
        sw = fmaf(wb.x, yw[4], sw); sw = fmaf(wb.y, yw[5], sw);
        sw = fmaf(wb.z, yw[6], sw); sw = fmaf(wb.w, yw[7], sw);
        ahp[c * H + l] = fsig(sh);
        awp[c * W + l] = fsig(sw);
    }
}

// ---------------------------------------------------------------------------
// k3 (R7-proven exact): 1024 blocks x 256 thr, 4 consecutive planes per block,
// DESCENDING plane order; a-maps staged in smem; 5-wide front-batched LDG.128;
// evict-first streaming stores.
// ---------------------------------------------------------------------------
__global__ __launch_bounds__(256) void k3_apply(const float* __restrict__ x,
                                                float* __restrict__ out) {
    __shared__ float  s_ah[4 * H];       // 4 planes of a_h (320 floats)
    __shared__ float4 s_aw[4 * 20];      // 4 planes of a_w as float4 (80 entries)
    const int pb  = 1023 - blockIdx.x;   // 4-plane group, descending
    const int tid = threadIdx.x;
    const size_t base = (size_t)pb * 6400;   // float4 base

    for (int i = tid; i < 4 * H; i += 256)
        s_ah[i] = g_ah[pb * 4 * H + i];
    if (tid < 4 * 20)
        s_aw[tid] = ((const float4*)g_aw)[pb * 4 * 20 + tid];
    __syncthreads();

    const float4* __restrict__ x4 = (const float4*)x;
    float4* __restrict__ o4 = (float4*)out;

    #pragma unroll
    for (int batch = 0; batch < 5; batch++) {
        float4 xv[5];
        int    idx[5];
        #pragma unroll
        for (int jj = 0; jj < 5; jj++) {
            idx[jj] = (batch * 5 + jj) * 256 + tid;      // [0, 6400)
            xv[jj]  = x4[base + idx[jj]];
        }
        #pragma unroll
        for (int jj = 0; jj < 5; jj++) {
            const int v   = idx[jj];
            const int lp  = v / 1600;                    // local plane 0..3
            const int rem = v - lp * 1600;
            const int hh  = rem / 20;
            const int q   = rem - hh * 20;
            const float  ah  = s_ah[lp * H + hh];
            const float4 aw4 = s_aw[lp * 20 + q];
            float4 r;
            r.x = xv[jj].x * (ah * aw4.x);
            r.y = xv[jj].y * (ah * aw4.y);
            r.z = xv[jj].z * (ah * aw4.z);
            r.w = xv[jj].w * (ah * aw4.w);
            __stcs(o4 + base + v, r);
        }
    }
}

// ---------------------------------------------------------------------------
extern "C" void kernel_launch(void* const* d_in, const int* in_sizes, int n_in,
                              void* d_out, int out_size) {
    const float* x        = (const float*)d_in[0];
    const float* w_fc     = (const float*)d_in[1];
    const float* bn_gamma = (const float*)d_in[2];
    const float* bn_beta  = (const float*)d_in[3];
    const float* bn_mean  = (const float*)d_in[4];
    const float* bn_var   = (const float*)d_in[5];
    const float* w_h      = (const float*)d_in[6];
    const float* w_w      = (const float*)d_in[7];
    float* out = (float*)d_out;

    k1_means<<<NB * C, 320>>>(x);
    k2_attn<<<dim3(16 + PF_BLOCKS, 2), 320>>>(x, w_fc, bn_gamma, bn_beta,
                                              bn_mean, bn_var, w_h, w_w);
    k3_apply<<<1024, 256>>>(x, out);
}